// round 2
// baseline (speedup 1.0000x reference)
#include <cuda_runtime.h>
#include <cuda_bf16.h>

// ---------------------------------------------------------------------------
// Problem constants
//   B=8, H=W=128, C=192, NH=6, hd=32, WS=8
//   M = B*H*W = 131072 tokens
// ---------------------------------------------------------------------------
#define M_TOK   131072
#define C_DIM   192
#define QKV_N   576
#define NH      6
#define HD      32
#define WS      8

// Scratch (device globals — no allocation allowed in kernel_launch)
__device__ float g_qkv [M_TOK * QKV_N];   // 302 MB
__device__ float g_attn[M_TOK * C_DIM];   // 100 MB
__device__ float g_conv[M_TOK * C_DIM];   // 100 MB

// ---------------------------------------------------------------------------
// Generic tiled fp32 GEMM with bias:  C[M,N] = A[M,K] @ B[K,N] + bias[N]
// BM=BN=64, BK=16, 256 threads, 4x4 per-thread microtile.
// Assumes M%64==0, N%64==0, K%16==0, and 16B alignment of rows (K,N mult of 4).
// ---------------------------------------------------------------------------
__global__ __launch_bounds__(256)
void gemm_bias_kernel(const float* __restrict__ A,
                      const float* __restrict__ B,
                      const float* __restrict__ bias,
                      float* __restrict__ C,
                      int M, int N, int K)
{
    const int BM = 64, BN = 64, BK = 16;
    __shared__ float As[BK][BM];   // transposed A tile
    __shared__ float Bs[BK][BN];

    const int tid = threadIdx.x;
    const int bm = blockIdx.x * BM;
    const int bn = blockIdx.y * BN;

    const int tx = tid & 15;        // 0..15 -> N
    const int ty = tid >> 4;        // 0..15 -> M

    float acc[4][4] = {};

    // load indices
    const int arow  = tid >> 2;          // 0..63
    const int acol4 = (tid & 3) * 4;     // 0,4,8,12
    const int brow  = tid >> 4;          // 0..15
    const int bcol4 = (tid & 15) * 4;    // 0..60

    for (int k0 = 0; k0 < K; k0 += BK) {
        // A tile: rows bm..bm+63, cols k0..k0+15 (transpose into As)
        float4 av = *(const float4*)(A + (long)(bm + arow) * K + k0 + acol4);
        As[acol4 + 0][arow] = av.x;
        As[acol4 + 1][arow] = av.y;
        As[acol4 + 2][arow] = av.z;
        As[acol4 + 3][arow] = av.w;
        // B tile: rows k0..k0+15, cols bn..bn+63
        float4 bv = *(const float4*)(B + (long)(k0 + brow) * N + bn + bcol4);
        *(float4*)&Bs[brow][bcol4] = bv;
        __syncthreads();

        #pragma unroll
        for (int k = 0; k < BK; k++) {
            float4 a4 = *(const float4*)&As[k][ty * 4];
            float4 b4 = *(const float4*)&Bs[k][tx * 4];
            float a[4] = {a4.x, a4.y, a4.z, a4.w};
            float b[4] = {b4.x, b4.y, b4.z, b4.w};
            #pragma unroll
            for (int m = 0; m < 4; m++)
                #pragma unroll
                for (int n = 0; n < 4; n++)
                    acc[m][n] = fmaf(a[m], b[n], acc[m][n]);
        }
        __syncthreads();
    }

    float4 bb = *(const float4*)(bias + bn + tx * 4);
    #pragma unroll
    for (int m = 0; m < 4; m++) {
        float4 o;
        o.x = acc[m][0] + bb.x;
        o.y = acc[m][1] + bb.y;
        o.z = acc[m][2] + bb.z;
        o.w = acc[m][3] + bb.w;
        *(float4*)(C + (long)(bm + ty * 4 + m) * N + bn + tx * 4) = o;
    }
}

// ---------------------------------------------------------------------------
// Window attention: one block = one window x 2 heads.
// gridDim.x = 2048 windows, gridDim.y = 3 head-pairs, 128 threads.
// Thread t: local head n2 = t/64, token i = t%64.
// qkv layout: [B,H,W, 3C] with q at [0,192), k at [192,384), v at [384,576),
// head h occupies channels [h*32,(h+1)*32) within each 192 chunk.
// Output written directly in [B,H,W,C] (window reverse is just indexing).
// ---------------------------------------------------------------------------
__global__ __launch_bounds__(128)
void win_attn_kernel(const float* __restrict__ qkv, float* __restrict__ out)
{
    __shared__ float ks[2][64][HD];
    __shared__ float vs[2][64][HD];

    const int win = blockIdx.x;          // 0..2047
    const int b   = win >> 8;            // /256
    const int rem = win & 255;
    const int wh  = rem >> 4;
    const int ww  = rem & 15;

    const int t  = threadIdx.x;
    const int n2 = t >> 6;               // 0/1
    const int i  = t & 63;               // token in window
    const int head = blockIdx.y * 2 + n2;

    const int iy = i >> 3, ix = i & 7;
    const int gh = wh * WS + iy;
    const int gw = ww * WS + ix;

    const long base = ((long)((b * 128 + gh) * 128 + gw)) * QKV_N;
    const float* qp = qkv + base + head * HD;
    const float* kp = qkv + base + C_DIM + head * HD;
    const float* vp = qkv + base + 2 * C_DIM + head * HD;

    const float scale = 0.1767766952966369f;  // 1/sqrt(32)
    float q[HD];
    #pragma unroll
    for (int kk = 0; kk < HD; kk += 4) {
        float4 k4 = *(const float4*)(kp + kk);
        *(float4*)&ks[n2][i][kk] = k4;
        float4 v4 = *(const float4*)(vp + kk);
        *(float4*)&vs[n2][i][kk] = v4;
        float4 q4 = *(const float4*)(qp + kk);
        q[kk + 0] = q4.x * scale;
        q[kk + 1] = q4.y * scale;
        q[kk + 2] = q4.z * scale;
        q[kk + 3] = q4.w * scale;
    }
    __syncthreads();

    float p[64];
    float mx = -1e30f;
    #pragma unroll 4
    for (int j = 0; j < 64; j++) {
        float s = 0.f;
        #pragma unroll
        for (int kk = 0; kk < HD; kk++)
            s = fmaf(q[kk], ks[n2][j][kk], s);
        p[j] = s;
        mx = fmaxf(mx, s);
    }
    float sum = 0.f;
    #pragma unroll
    for (int j = 0; j < 64; j++) {
        p[j] = __expf(p[j] - mx);
        sum += p[j];
    }
    const float inv = 1.0f / sum;

    float acc[HD] = {};
    #pragma unroll 4
    for (int j = 0; j < 64; j++) {
        float pj = p[j] * inv;
        #pragma unroll
        for (int kk = 0; kk < HD; kk++)
            acc[kk] = fmaf(pj, vs[n2][j][kk], acc[kk]);
    }

    float* op = out + ((long)((b * 128 + gh) * 128 + gw)) * C_DIM + head * HD;
    #pragma unroll
    for (int kk = 0; kk < HD; kk += 4) {
        float4 o = make_float4(acc[kk], acc[kk + 1], acc[kk + 2], acc[kk + 3]);
        *(float4*)(op + kk) = o;
    }
}

// ---------------------------------------------------------------------------
// Depthwise 3x3 conv, pad 1, NHWC. One thread = 4 channels of one pixel.
// w_dw layout (3,3,1,C): [(ky*3+kx)*C + c]
// ---------------------------------------------------------------------------
__global__ __launch_bounds__(256)
void dwconv_kernel(const float* __restrict__ in,
                   const float* __restrict__ wdw,
                   const float* __restrict__ bdw,
                   float* __restrict__ out)
{
    const int NC4 = C_DIM / 4;  // 48
    int idx = blockIdx.x * blockDim.x + threadIdx.x;
    if (idx >= M_TOK * NC4) return;
    const int c4 = idx % NC4;
    int r = idx / NC4;
    const int w = r & 127; r >>= 7;
    const int h = r & 127; r >>= 7;
    const int b = r;
    const int c = c4 * 4;

    float4 acc = *(const float4*)(bdw + c);
    #pragma unroll
    for (int ky = 0; ky < 3; ky++) {
        int hh = h + ky - 1;
        if (hh < 0 || hh > 127) continue;
        #pragma unroll
        for (int kx = 0; kx < 3; kx++) {
            int ww = w + kx - 1;
            if (ww < 0 || ww > 127) continue;
            float4 xi = *(const float4*)(in + ((long)((b * 128 + hh) * 128 + ww)) * C_DIM + c);
            float4 wk = *(const float4*)(wdw + (ky * 3 + kx) * C_DIM + c);
            acc.x = fmaf(xi.x, wk.x, acc.x);
            acc.y = fmaf(xi.y, wk.y, acc.y);
            acc.z = fmaf(xi.z, wk.z, acc.z);
            acc.w = fmaf(xi.w, wk.w, acc.w);
        }
    }
    *(float4*)(out + ((long)((b * 128 + h) * 128 + w)) * C_DIM + c) = acc;
}

// ---------------------------------------------------------------------------
extern "C" void kernel_launch(void* const* d_in, const int* in_sizes, int n_in,
                              void* d_out, int out_size)
{
    const float* x      = (const float*)d_in[0];
    const float* w_qkv  = (const float*)d_in[1];
    const float* b_qkv  = (const float*)d_in[2];
    const float* w_dw   = (const float*)d_in[3];
    const float* b_dw   = (const float*)d_in[4];
    const float* w_proj = (const float*)d_in[5];
    const float* b_proj = (const float*)d_in[6];
    float* out = (float*)d_out;

    float *qkv, *attn, *conv;
    cudaGetSymbolAddress((void**)&qkv,  g_qkv);
    cudaGetSymbolAddress((void**)&attn, g_attn);
    cudaGetSymbolAddress((void**)&conv, g_conv);

    // 1) qkv = x @ w_qkv + b_qkv   [131072, 576]
    gemm_bias_kernel<<<dim3(M_TOK / 64, QKV_N / 64), 256>>>(
        x, w_qkv, b_qkv, qkv, M_TOK, QKV_N, C_DIM);

    // 2) window attention -> [B,H,W,C]
    win_attn_kernel<<<dim3(2048, 3), 128>>>(qkv, attn);

    // 3) depthwise 3x3 conv
    dwconv_kernel<<<(M_TOK * (C_DIM / 4) + 255) / 256, 256>>>(attn, w_dw, b_dw, conv);

    // 4) proj: out = conv @ w_proj + b_proj   [131072, 192]
    gemm_bias_kernel<<<dim3(M_TOK / 64, C_DIM / 64), 256>>>(
        conv, w_proj, b_proj, out, M_TOK, C_DIM, C_DIM);
}

// round 13
// speedup vs baseline: 1.3122x; 1.3122x over previous
#include <cuda_runtime.h>
#include <cuda_fp16.h>
#include <cstdint>

// ---------------------------------------------------------------------------
// Problem constants:  B=8, H=W=128, C=192, NH=6, hd=32, WS=8, M = 131072
// ---------------------------------------------------------------------------
#define M_TOK   131072
#define C_DIM   192
#define QKV_N   576
#define NH      6
#define HD      32
#define WS      8

// Scratch (device globals — no allocation allowed). All fp32 (R1-proven glue).
__device__ float g_qkv [M_TOK * QKV_N];   // 302 MB
__device__ float g_attn[M_TOK * C_DIM];   // 100 MB
__device__ float g_conv[M_TOK * C_DIM];   // 100 MB

// ---------------------------------------------------------------------------
// mma.m16n8k16 (fp16 in, fp32 accum) — baseline PTX, valid on sm_103 target
// ---------------------------------------------------------------------------
__device__ __forceinline__ void mma_16816(float& c0, float& c1, float& c2, float& c3,
                                          uint32_t a0, uint32_t a1, uint32_t a2, uint32_t a3,
                                          uint32_t b0, uint32_t b1) {
    asm volatile(
        "mma.sync.aligned.m16n8k16.row.col.f32.f16.f16.f32 "
        "{%0,%1,%2,%3}, {%4,%5,%6,%7}, {%8,%9}, {%0,%1,%2,%3};"
        : "+f"(c0), "+f"(c1), "+f"(c2), "+f"(c3)
        : "r"(a0), "r"(a1), "r"(a2), "r"(a3), "r"(b0), "r"(b1));
}

// ---------------------------------------------------------------------------
// HMMA GEMM, fully self-contained:
//   C[M,Ntot]_f32 = A[M,192]_f32 @ W[192,Ntot]_f32 + bias
// A converted fp32->fp16 during smem store. W transposed ([K,N] -> Bs[n][k])
// and converted during smem store. No external fp16 buffers, no wtrans/f2h.
// BM=128, full K=192 resident. N swept in 64-wide slabs (single buffer).
// 256 thr = 8 warps, warp grid 4(M) x 2(N), warp tile 32x32.
// Smem rows padded to GP=200 halves (400B) -> conflict-free fragment loads.
// ---------------------------------------------------------------------------
#define GP 200
#define GSM_TOTAL ((128 + 64) * GP * 2)   // 76800 bytes

__global__ __launch_bounds__(256)
void gemm_hmma_kernel(const float* __restrict__ A,
                      const float* __restrict__ W,      // [192, Ntot] original
                      const float* __restrict__ bias,
                      float* __restrict__ Cout,
                      int Ntot)
{
    extern __shared__ __half sh[];
    __half* As = sh;               // [128][GP]
    __half* Bs = sh + 128 * GP;    // [64][GP]  (Bs[n][k])

    const int tid  = threadIdx.x;
    const int wid  = tid >> 5, lane = tid & 31;
    const int wm   = wid >> 1;     // 0..3 (M)
    const int wn   = wid & 1;      // 0..1 (N)
    const int g    = lane >> 2;    // 0..7
    const int tq   = lane & 3;     // 0..3
    const int bm   = blockIdx.x * 128;
    const int NB   = Ntot / 64;

    // ---- load A tile (128 x 192 fp32 -> fp16) once ----
    for (int idx = tid; idx < 128 * 48; idx += 256) {
        int row = idx / 48, c4 = idx % 48;
        float4 v = *(const float4*)(A + (size_t)(bm + row) * 192 + c4 * 4);
        uint2 pk;
        ((__half2*)&pk)[0] = __floats2half2_rn(v.x, v.y);
        ((__half2*)&pk)[1] = __floats2half2_rn(v.z, v.w);
        *(uint2*)(As + row * GP + c4 * 4) = pk;
    }

    for (int nb = 0; nb < NB; nb++) {
        // ---- load B slab: W[k][nb*64 + nl] -> Bs[nl][k], fp32 -> fp16 ----
        // consecutive tid -> consecutive nl: coalesced gmem reads.
        for (int idx = tid; idx < 192 * 64; idx += 256) {
            int k = idx >> 6, nl = idx & 63;
            float v = W[(size_t)k * Ntot + nb * 64 + nl];
            Bs[nl * GP + k] = __float2half(v);
        }
        __syncthreads();

        float acc[2][4][4] = {};

        #pragma unroll
        for (int ks = 0; ks < 12; ks++) {
            const int k0 = ks * 16 + tq * 2;
            uint32_t a[2][4], b[4][2];
            #pragma unroll
            for (int mt = 0; mt < 2; mt++) {
                const __half* ar = As + (wm * 32 + mt * 16 + g) * GP + k0;
                a[mt][0] = *(const uint32_t*)(ar);            // row g,   k0..k0+1
                a[mt][1] = *(const uint32_t*)(ar + 8 * GP);   // row g+8
                a[mt][2] = *(const uint32_t*)(ar + 8);        // row g,   k0+8
                a[mt][3] = *(const uint32_t*)(ar + 8 * GP + 8);
            }
            #pragma unroll
            for (int nj = 0; nj < 4; nj++) {
                const __half* br = Bs + (wn * 32 + nj * 8 + g) * GP + k0;
                b[nj][0] = *(const uint32_t*)(br);            // n g, k0..k0+1
                b[nj][1] = *(const uint32_t*)(br + 8);        // n g, k0+8
            }
            #pragma unroll
            for (int mt = 0; mt < 2; mt++)
                #pragma unroll
                for (int nj = 0; nj < 4; nj++)
                    mma_16816(acc[mt][nj][0], acc[mt][nj][1],
                              acc[mt][nj][2], acc[mt][nj][3],
                              a[mt][0], a[mt][1], a[mt][2], a[mt][3],
                              b[nj][0], b[nj][1]);
        }

        // ---- epilogue for this slab (fp32 out) ----
        #pragma unroll
        for (int mt = 0; mt < 2; mt++) {
            #pragma unroll
            for (int nj = 0; nj < 4; nj++) {
                int row = bm + wm * 32 + mt * 16 + g;
                int col = nb * 64 + wn * 32 + nj * 8 + tq * 2;
                float2 bb = *(const float2*)(bias + col);
                *(float2*)(Cout + (size_t)row * Ntot + col) =
                    make_float2(acc[mt][nj][0] + bb.x, acc[mt][nj][1] + bb.y);
                *(float2*)(Cout + (size_t)(row + 8) * Ntot + col) =
                    make_float2(acc[mt][nj][2] + bb.x, acc[mt][nj][3] + bb.y);
            }
        }
        __syncthreads();
    }
}

// ---------------------------------------------------------------------------
// Window attention — EXACT R1 version (fp32, proven at rel_err 3.3e-7).
// One block = one window x 2 heads. grid (2048, 3), 128 threads.
// ---------------------------------------------------------------------------
__global__ __launch_bounds__(128)
void win_attn_kernel(const float* __restrict__ qkv, float* __restrict__ out)
{
    __shared__ float ks[2][64][HD];
    __shared__ float vs[2][64][HD];

    const int win = blockIdx.x;          // 0..2047
    const int b   = win >> 8;
    const int rem = win & 255;
    const int wh  = rem >> 4;
    const int ww  = rem & 15;

    const int t  = threadIdx.x;
    const int n2 = t >> 6;
    const int i  = t & 63;
    const int head = blockIdx.y * 2 + n2;

    const int iy = i >> 3, ix = i & 7;
    const int gh = wh * WS + iy;
    const int gw = ww * WS + ix;

    const long base = ((long)((b * 128 + gh) * 128 + gw)) * QKV_N;
    const float* qp = qkv + base + head * HD;
    const float* kp = qkv + base + C_DIM + head * HD;
    const float* vp = qkv + base + 2 * C_DIM + head * HD;

    const float scale = 0.1767766952966369f;  // 1/sqrt(32)
    float q[HD];
    #pragma unroll
    for (int kk = 0; kk < HD; kk += 4) {
        float4 k4 = *(const float4*)(kp + kk);
        *(float4*)&ks[n2][i][kk] = k4;
        float4 v4 = *(const float4*)(vp + kk);
        *(float4*)&vs[n2][i][kk] = v4;
        float4 q4 = *(const float4*)(qp + kk);
        q[kk + 0] = q4.x * scale;
        q[kk + 1] = q4.y * scale;
        q[kk + 2] = q4.z * scale;
        q[kk + 3] = q4.w * scale;
    }
    __syncthreads();

    float p[64];
    float mx = -1e30f;
    #pragma unroll 4
    for (int j = 0; j < 64; j++) {
        float s = 0.f;
        #pragma unroll
        for (int kk = 0; kk < HD; kk++)
            s = fmaf(q[kk], ks[n2][j][kk], s);
        p[j] = s;
        mx = fmaxf(mx, s);
    }
    float sum = 0.f;
    #pragma unroll
    for (int j = 0; j < 64; j++) {
        p[j] = __expf(p[j] - mx);
        sum += p[j];
    }
    const float inv = 1.0f / sum;

    float acc[HD] = {};
    #pragma unroll 4
    for (int j = 0; j < 64; j++) {
        float pj = p[j] * inv;
        #pragma unroll
        for (int kk = 0; kk < HD; kk++)
            acc[kk] = fmaf(pj, vs[n2][j][kk], acc[kk]);
    }

    float* op = out + ((long)((b * 128 + gh) * 128 + gw)) * C_DIM + head * HD;
    #pragma unroll
    for (int kk = 0; kk < HD; kk += 4) {
        float4 o = make_float4(acc[kk], acc[kk + 1], acc[kk + 2], acc[kk + 3]);
        *(float4*)(op + kk) = o;
    }
}

// ---------------------------------------------------------------------------
// Depthwise 3x3 conv — EXACT R1 version (fp32, proven).
// ---------------------------------------------------------------------------
__global__ __launch_bounds__(256)
void dwconv_kernel(const float* __restrict__ in,
                   const float* __restrict__ wdw,
                   const float* __restrict__ bdw,
                   float* __restrict__ out)
{
    const int NC4 = C_DIM / 4;  // 48
    int idx = blockIdx.x * blockDim.x + threadIdx.x;
    if (idx >= M_TOK * NC4) return;
    const int c4 = idx % NC4;
    int r = idx / NC4;
    const int w = r & 127; r >>= 7;
    const int h = r & 127; r >>= 7;
    const int b = r;
    const int c = c4 * 4;

    float4 acc = *(const float4*)(bdw + c);
    #pragma unroll
    for (int ky = 0; ky < 3; ky++) {
        int hh = h + ky - 1;
        if (hh < 0 || hh > 127) continue;
        #pragma unroll
        for (int kx = 0; kx < 3; kx++) {
            int ww = w + kx - 1;
            if (ww < 0 || ww > 127) continue;
            float4 xi = *(const float4*)(in + ((long)((b * 128 + hh) * 128 + ww)) * C_DIM + c);
            float4 wk = *(const float4*)(wdw + (ky * 3 + kx) * C_DIM + c);
            acc.x = fmaf(xi.x, wk.x, acc.x);
            acc.y = fmaf(xi.y, wk.y, acc.y);
            acc.z = fmaf(xi.z, wk.z, acc.z);
            acc.w = fmaf(xi.w, wk.w, acc.w);
        }
    }
    *(float4*)(out + ((long)((b * 128 + h) * 128 + w)) * C_DIM + c) = acc;
}

// ---------------------------------------------------------------------------
extern "C" void kernel_launch(void* const* d_in, const int* in_sizes, int n_in,
                              void* d_out, int out_size)
{
    const float* x      = (const float*)d_in[0];
    const float* w_qkv  = (const float*)d_in[1];
    const float* b_qkv  = (const float*)d_in[2];
    const float* w_dw   = (const float*)d_in[3];
    const float* b_dw   = (const float*)d_in[4];
    const float* w_proj = (const float*)d_in[5];
    const float* b_proj = (const float*)d_in[6];
    float* out = (float*)d_out;

    float *qkv, *attn, *conv;
    cudaGetSymbolAddress((void**)&qkv,  g_qkv);
    cudaGetSymbolAddress((void**)&attn, g_attn);
    cudaGetSymbolAddress((void**)&conv, g_conv);

    // idempotent; called every time (no static guards allowed)
    cudaFuncSetAttribute(gemm_hmma_kernel,
                         cudaFuncAttributeMaxDynamicSharedMemorySize, GSM_TOTAL);

    // 1) qkv = x @ w_qkv + b_qkv   [131072, 576] fp32
    gemm_hmma_kernel<<<M_TOK / 128, 256, GSM_TOTAL>>>(
        x, w_qkv, b_qkv, qkv, QKV_N);

    // 2) window attention -> [B,H,W,C] fp32 (R1-proven)
    win_attn_kernel<<<dim3(2048, 3), 128>>>(qkv, attn);

    // 3) depthwise 3x3 conv fp32 (R1-proven)
    dwconv_kernel<<<(M_TOK * (C_DIM / 4) + 255) / 256, 256>>>(attn, w_dw, b_dw, conv);

    // 4) proj: out = conv @ w_proj + b_proj   [131072, 192] fp32
    gemm_hmma_kernel<<<M_TOK / 128, 256, GSM_TOTAL>>>(
        conv, w_proj, b_proj, out, C_DIM);
}

// round 14
// speedup vs baseline: 2.0101x; 1.5318x over previous
#include <cuda_runtime.h>
#include <cuda_fp16.h>
#include <cstdint>

// ---------------------------------------------------------------------------
// Problem constants:  B=8, H=W=128, C=192, NH=6, hd=32, WS=8, M = 131072
// ---------------------------------------------------------------------------
#define M_TOK   131072
#define C_DIM   192
#define QKV_N   576
#define NH      6
#define HD      32
#define WS      8

// Scratch (device globals — no allocation allowed). fp16 intermediates.
__device__ __half g_qkvh [M_TOK * QKV_N];   // 151 MB
__device__ __half g_attnh[M_TOK * C_DIM];   // 50 MB
__device__ __half g_convh[M_TOK * C_DIM];   // 50 MB

// ---------------------------------------------------------------------------
// mma.m16n8k16 (fp16 in, fp32 accum)
// ---------------------------------------------------------------------------
__device__ __forceinline__ void mma_16816(float& c0, float& c1, float& c2, float& c3,
                                          uint32_t a0, uint32_t a1, uint32_t a2, uint32_t a3,
                                          uint32_t b0, uint32_t b1) {
    asm volatile(
        "mma.sync.aligned.m16n8k16.row.col.f32.f16.f16.f32 "
        "{%0,%1,%2,%3}, {%4,%5,%6,%7}, {%8,%9}, {%0,%1,%2,%3};"
        : "+f"(c0), "+f"(c1), "+f"(c2), "+f"(c3)
        : "r"(a0), "r"(a1), "r"(a2), "r"(a3), "r"(b0), "r"(b1));
}

// ---------------------------------------------------------------------------
// HMMA GEMM (R12-proven core):
//   C[M,Ntot] = A[M,192] @ W[192,Ntot]_f32 + bias
// A read as fp32 (a_half=0, converted in-smem) or fp16 (a_half=1, copied).
// W transposed+converted in-kernel ([K,N] -> Bs[n][k]).
// Output fp32 (store_half=0) or fp16 (store_half=1).
// BM=128, full K=192 resident; N swept in 64-wide slabs.
// 256 thr = 8 warps, warp grid 4(M) x 2(N), warp tile 32x32. GP=200 pad.
// ---------------------------------------------------------------------------
#define GP 200
#define GSM_TOTAL ((128 + 64) * GP * 2)   // 76800 bytes

__global__ __launch_bounds__(256)
void gemm_hmma_kernel(const void* __restrict__ Ain, int a_half,
                      const float* __restrict__ W,
                      const float* __restrict__ bias,
                      void* __restrict__ Cout,
                      int Ntot, int store_half)
{
    extern __shared__ __half sh[];
    __half* As = sh;               // [128][GP]
    __half* Bs = sh + 128 * GP;    // [64][GP]  (Bs[n][k])

    const int tid  = threadIdx.x;
    const int wid  = tid >> 5, lane = tid & 31;
    const int wm   = wid >> 1;     // 0..3 (M)
    const int wn   = wid & 1;      // 0..1 (N)
    const int g    = lane >> 2;    // 0..7
    const int tq   = lane & 3;     // 0..3
    const int bm   = blockIdx.x * 128;
    const int NB   = Ntot / 64;

    // ---- load A tile (128 x 192) once ----
    if (a_half) {
        const __half* A = (const __half*)Ain;
        for (int idx = tid; idx < 128 * 24; idx += 256) {
            int row = idx / 24, c8 = idx % 24;
            uint4 v = *(const uint4*)(A + (size_t)(bm + row) * 192 + c8 * 8);
            *(uint4*)(As + row * GP + c8 * 8) = v;
        }
    } else {
        const float* A = (const float*)Ain;
        for (int idx = tid; idx < 128 * 48; idx += 256) {
            int row = idx / 48, c4 = idx % 48;
            float4 v = *(const float4*)(A + (size_t)(bm + row) * 192 + c4 * 4);
            uint2 pk;
            ((__half2*)&pk)[0] = __floats2half2_rn(v.x, v.y);
            ((__half2*)&pk)[1] = __floats2half2_rn(v.z, v.w);
            *(uint2*)(As + row * GP + c4 * 4) = pk;
        }
    }

    for (int nb = 0; nb < NB; nb++) {
        // ---- B slab: W[k][nb*64+nl] -> Bs[nl][k] (fp32 -> fp16) ----
        for (int idx = tid; idx < 192 * 64; idx += 256) {
            int k = idx >> 6, nl = idx & 63;
            float v = W[(size_t)k * Ntot + nb * 64 + nl];
            Bs[nl * GP + k] = __float2half(v);
        }
        __syncthreads();

        float acc[2][4][4] = {};

        #pragma unroll
        for (int ks = 0; ks < 12; ks++) {
            const int k0 = ks * 16 + tq * 2;
            uint32_t a[2][4], b[4][2];
            #pragma unroll
            for (int mt = 0; mt < 2; mt++) {
                const __half* ar = As + (wm * 32 + mt * 16 + g) * GP + k0;
                a[mt][0] = *(const uint32_t*)(ar);
                a[mt][1] = *(const uint32_t*)(ar + 8 * GP);
                a[mt][2] = *(const uint32_t*)(ar + 8);
                a[mt][3] = *(const uint32_t*)(ar + 8 * GP + 8);
            }
            #pragma unroll
            for (int nj = 0; nj < 4; nj++) {
                const __half* br = Bs + (wn * 32 + nj * 8 + g) * GP + k0;
                b[nj][0] = *(const uint32_t*)(br);
                b[nj][1] = *(const uint32_t*)(br + 8);
            }
            #pragma unroll
            for (int mt = 0; mt < 2; mt++)
                #pragma unroll
                for (int nj = 0; nj < 4; nj++)
                    mma_16816(acc[mt][nj][0], acc[mt][nj][1],
                              acc[mt][nj][2], acc[mt][nj][3],
                              a[mt][0], a[mt][1], a[mt][2], a[mt][3],
                              b[nj][0], b[nj][1]);
        }

        // ---- epilogue for this slab ----
        #pragma unroll
        for (int mt = 0; mt < 2; mt++) {
            #pragma unroll
            for (int nj = 0; nj < 4; nj++) {
                int row = bm + wm * 32 + mt * 16 + g;
                int col = nb * 64 + wn * 32 + nj * 8 + tq * 2;
                float2 bb = *(const float2*)(bias + col);
                float v0 = acc[mt][nj][0] + bb.x;
                float v1 = acc[mt][nj][1] + bb.y;
                float v2 = acc[mt][nj][2] + bb.x;
                float v3 = acc[mt][nj][3] + bb.y;
                if (store_half) {
                    __half* o = (__half*)Cout;
                    *(__half2*)(o + (size_t)row * Ntot + col) = __floats2half2_rn(v0, v1);
                    *(__half2*)(o + (size_t)(row + 8) * Ntot + col) = __floats2half2_rn(v2, v3);
                } else {
                    float* o = (float*)Cout;
                    *(float2*)(o + (size_t)row * Ntot + col) = make_float2(v0, v1);
                    *(float2*)(o + (size_t)(row + 8) * Ntot + col) = make_float2(v2, v3);
                }
            }
        }
        __syncthreads();
    }
}

// ---------------------------------------------------------------------------
// Window attention: fp16 I/O, fp32 math. Rewritten from the R12-proven fp32
// kernel; output staging is uint4 o[4] = 32 halves (the R2 bug was o[2]).
// One block = one window x 2 heads. grid (2048, 3), 128 threads.
// ---------------------------------------------------------------------------
__global__ __launch_bounds__(128)
void win_attn_kernel(const __half* __restrict__ qkv, __half* __restrict__ out)
{
    __shared__ float ks[2][64][HD];
    __shared__ float vs[2][64][HD];

    const int win = blockIdx.x;          // 0..2047
    const int b   = win >> 8;
    const int rem = win & 255;
    const int wh  = rem >> 4;
    const int ww  = rem & 15;

    const int t  = threadIdx.x;
    const int n2 = t >> 6;
    const int i  = t & 63;
    const int head = blockIdx.y * 2 + n2;

    const int iy = i >> 3, ix = i & 7;
    const int gh = wh * WS + iy;
    const int gw = ww * WS + ix;

    const size_t base = ((size_t)((b * 128 + gh) * 128 + gw)) * QKV_N;
    const __half* qp = qkv + base + head * HD;
    const __half* kp = qkv + base + C_DIM + head * HD;
    const __half* vp = qkv + base + 2 * C_DIM + head * HD;

    const float scale = 0.1767766952966369f;  // 1/sqrt(32)
    float q[HD];
    #pragma unroll
    for (int c = 0; c < 4; c++) {            // 4 x 8 halves = 32
        uint4 kr = *(const uint4*)(kp + c * 8);
        uint4 vr = *(const uint4*)(vp + c * 8);
        uint4 qr = *(const uint4*)(qp + c * 8);
        const __half2* kh = (const __half2*)&kr;
        const __half2* vh = (const __half2*)&vr;
        const __half2* qh = (const __half2*)&qr;
        #pragma unroll
        for (int j = 0; j < 4; j++) {
            float2 f = __half22float2(kh[j]);
            ks[n2][i][c * 8 + 2 * j]     = f.x;
            ks[n2][i][c * 8 + 2 * j + 1] = f.y;
            f = __half22float2(vh[j]);
            vs[n2][i][c * 8 + 2 * j]     = f.x;
            vs[n2][i][c * 8 + 2 * j + 1] = f.y;
            f = __half22float2(qh[j]);
            q[c * 8 + 2 * j]     = f.x * scale;
            q[c * 8 + 2 * j + 1] = f.y * scale;
        }
    }
    __syncthreads();

    float p[64];
    float mx = -1e30f;
    #pragma unroll 4
    for (int j = 0; j < 64; j++) {
        float s = 0.f;
        #pragma unroll
        for (int kk = 0; kk < HD; kk++)
            s = fmaf(q[kk], ks[n2][j][kk], s);
        p[j] = s;
        mx = fmaxf(mx, s);
    }
    float sum = 0.f;
    #pragma unroll
    for (int j = 0; j < 64; j++) {
        p[j] = __expf(p[j] - mx);
        sum += p[j];
    }
    const float inv = 1.0f / sum;

    float acc[HD] = {};
    #pragma unroll 4
    for (int j = 0; j < 64; j++) {
        float pj = p[j] * inv;
        #pragma unroll
        for (int kk = 0; kk < HD; kk++)
            acc[kk] = fmaf(pj, vs[n2][j][kk], acc[kk]);
    }

    __half* op = out + ((size_t)((b * 128 + gh) * 128 + gw)) * C_DIM + head * HD;
    uint4 o[4];                               // 4 x 16B = 32 halves (FIXED)
    __half2* oh = (__half2*)o;
    #pragma unroll
    for (int j = 0; j < 16; j++)
        oh[j] = __floats2half2_rn(acc[2 * j], acc[2 * j + 1]);
    *(uint4*)(op)      = o[0];
    *(uint4*)(op + 8)  = o[1];
    *(uint4*)(op + 16) = o[2];
    *(uint4*)(op + 24) = o[3];
}

// ---------------------------------------------------------------------------
// Depthwise 3x3 conv, pad 1, NHWC, fp16 I/O, fp32 math.
// One thread = 8 channels of one pixel.
// ---------------------------------------------------------------------------
__global__ __launch_bounds__(256)
void dwconv_kernel(const __half* __restrict__ in,
                   const float* __restrict__ wdw,
                   const float* __restrict__ bdw,
                   __half* __restrict__ out)
{
    const int NC8 = C_DIM / 8;  // 24
    int idx = blockIdx.x * blockDim.x + threadIdx.x;
    if (idx >= M_TOK * NC8) return;
    const int c8 = idx % NC8;
    int r = idx / NC8;
    const int w = r & 127; r >>= 7;
    const int h = r & 127; r >>= 7;
    const int b = r;
    const int c = c8 * 8;

    float acc[8];
    {
        float4 b0 = *(const float4*)(bdw + c);
        float4 b1 = *(const float4*)(bdw + c + 4);
        acc[0] = b0.x; acc[1] = b0.y; acc[2] = b0.z; acc[3] = b0.w;
        acc[4] = b1.x; acc[5] = b1.y; acc[6] = b1.z; acc[7] = b1.w;
    }
    #pragma unroll
    for (int ky = 0; ky < 3; ky++) {
        int hh = h + ky - 1;
        if (hh < 0 || hh > 127) continue;
        #pragma unroll
        for (int kx = 0; kx < 3; kx++) {
            int ww = w + kx - 1;
            if (ww < 0 || ww > 127) continue;
            uint4 raw = *(const uint4*)(in + ((size_t)((b * 128 + hh) * 128 + ww)) * C_DIM + c);
            const __half2* xh = (const __half2*)&raw;
            float4 w0 = *(const float4*)(wdw + (ky * 3 + kx) * C_DIM + c);
            float4 w1 = *(const float4*)(wdw + (ky * 3 + kx) * C_DIM + c + 4);
            float wk[8] = {w0.x, w0.y, w0.z, w0.w, w1.x, w1.y, w1.z, w1.w};
            #pragma unroll
            for (int j = 0; j < 4; j++) {
                float2 f = __half22float2(xh[j]);
                acc[2 * j]     = fmaf(f.x, wk[2 * j],     acc[2 * j]);
                acc[2 * j + 1] = fmaf(f.y, wk[2 * j + 1], acc[2 * j + 1]);
            }
        }
    }
    uint4 o;
    __half2* oh = (__half2*)&o;
    #pragma unroll
    for (int j = 0; j < 4; j++)
        oh[j] = __floats2half2_rn(acc[2 * j], acc[2 * j + 1]);
    *(uint4*)(out + ((size_t)((b * 128 + h) * 128 + w)) * C_DIM + c) = o;
}

// ---------------------------------------------------------------------------
extern "C" void kernel_launch(void* const* d_in, const int* in_sizes, int n_in,
                              void* d_out, int out_size)
{
    const float* x      = (const float*)d_in[0];
    const float* w_qkv  = (const float*)d_in[1];
    const float* b_qkv  = (const float*)d_in[2];
    const float* w_dw   = (const float*)d_in[3];
    const float* b_dw   = (const float*)d_in[4];
    const float* w_proj = (const float*)d_in[5];
    const float* b_proj = (const float*)d_in[6];
    float* out = (float*)d_out;

    __half *qkvh, *attnh, *convh;
    cudaGetSymbolAddress((void**)&qkvh,  g_qkvh);
    cudaGetSymbolAddress((void**)&attnh, g_attnh);
    cudaGetSymbolAddress((void**)&convh, g_convh);

    // idempotent; called every time (no static guards allowed)
    cudaFuncSetAttribute(gemm_hmma_kernel,
                         cudaFuncAttributeMaxDynamicSharedMemorySize, GSM_TOTAL);

    // 1) qkv = x @ w_qkv + b_qkv   -> fp16 [131072, 576]
    gemm_hmma_kernel<<<M_TOK / 128, 256, GSM_TOTAL>>>(
        x, 0, w_qkv, b_qkv, qkvh, QKV_N, 1);

    // 2) window attention (fp16 -> fp16)
    win_attn_kernel<<<dim3(2048, 3), 128>>>(qkvh, attnh);

    // 3) depthwise 3x3 conv (fp16 -> fp16)
    dwconv_kernel<<<(M_TOK * (C_DIM / 8) + 255) / 256, 256>>>(attnh, w_dw, b_dw, convh);

    // 4) proj: out = conv @ w_proj + b_proj -> fp32 [131072, 192]
    gemm_hmma_kernel<<<M_TOK / 128, 256, GSM_TOTAL>>>(
        convh, 1, w_proj, b_proj, out, C_DIM, 0);
}

// round 15
// speedup vs baseline: 2.4390x; 1.2134x over previous
#include <cuda_runtime.h>
#include <cuda_fp16.h>
#include <cstdint>

// ---------------------------------------------------------------------------
// Problem constants:  B=8, H=W=128, C=192, NH=6, hd=32, WS=8, M = 131072
// ---------------------------------------------------------------------------
#define M_TOK   131072
#define C_DIM   192
#define QKV_N   576
#define NH      6
#define HD      32
#define WS      8

// Scratch (device globals — no allocation allowed). fp16 intermediates.
__device__ __half g_qkvh [M_TOK * QKV_N];   // 151 MB
__device__ __half g_attnh[M_TOK * C_DIM];   // 50 MB

// ---------------------------------------------------------------------------
// mma.m16n8k16 (fp16 in, fp32 accum)
// ---------------------------------------------------------------------------
__device__ __forceinline__ void mma_16816(float* c,
                                          uint32_t a0, uint32_t a1, uint32_t a2, uint32_t a3,
                                          uint32_t b0, uint32_t b1) {
    asm volatile(
        "mma.sync.aligned.m16n8k16.row.col.f32.f16.f16.f32 "
        "{%0,%1,%2,%3}, {%4,%5,%6,%7}, {%8,%9}, {%0,%1,%2,%3};"
        : "+f"(c[0]), "+f"(c[1]), "+f"(c[2]), "+f"(c[3])
        : "r"(a0), "r"(a1), "r"(a2), "r"(a3), "r"(b0), "r"(b1));
}

// ---------------------------------------------------------------------------
// HMMA GEMM (R12/R13-proven core):
//   C[M,Ntot] = A[M,192] @ W[192,Ntot]_f32 + bias
// ---------------------------------------------------------------------------
#define GP 200
#define GSM_TOTAL ((128 + 64) * GP * 2)   // 76800 bytes

__global__ __launch_bounds__(256)
void gemm_hmma_kernel(const void* __restrict__ Ain, int a_half,
                      const float* __restrict__ W,
                      const float* __restrict__ bias,
                      void* __restrict__ Cout,
                      int Ntot, int store_half)
{
    extern __shared__ __half sh[];
    __half* As = sh;               // [128][GP]
    __half* Bs = sh + 128 * GP;    // [64][GP]  (Bs[n][k])

    const int tid  = threadIdx.x;
    const int wid  = tid >> 5, lane = tid & 31;
    const int wm   = wid >> 1;
    const int wn   = wid & 1;
    const int g    = lane >> 2;
    const int tq   = lane & 3;
    const int bm   = blockIdx.x * 128;
    const int NB   = Ntot / 64;

    if (a_half) {
        const __half* A = (const __half*)Ain;
        for (int idx = tid; idx < 128 * 24; idx += 256) {
            int row = idx / 24, c8 = idx % 24;
            uint4 v = *(const uint4*)(A + (size_t)(bm + row) * 192 + c8 * 8);
            *(uint4*)(As + row * GP + c8 * 8) = v;
        }
    } else {
        const float* A = (const float*)Ain;
        for (int idx = tid; idx < 128 * 48; idx += 256) {
            int row = idx / 48, c4 = idx % 48;
            float4 v = *(const float4*)(A + (size_t)(bm + row) * 192 + c4 * 4);
            uint2 pk;
            ((__half2*)&pk)[0] = __floats2half2_rn(v.x, v.y);
            ((__half2*)&pk)[1] = __floats2half2_rn(v.z, v.w);
            *(uint2*)(As + row * GP + c4 * 4) = pk;
        }
    }

    for (int nb = 0; nb < NB; nb++) {
        for (int idx = tid; idx < 192 * 64; idx += 256) {
            int k = idx >> 6, nl = idx & 63;
            Bs[nl * GP + k] = __float2half(W[(size_t)k * Ntot + nb * 64 + nl]);
        }
        __syncthreads();

        float acc[2][4][4] = {};
        #pragma unroll
        for (int ks = 0; ks < 12; ks++) {
            const int k0 = ks * 16 + tq * 2;
            uint32_t a[2][4], b[4][2];
            #pragma unroll
            for (int mt = 0; mt < 2; mt++) {
                const __half* ar = As + (wm * 32 + mt * 16 + g) * GP + k0;
                a[mt][0] = *(const uint32_t*)(ar);
                a[mt][1] = *(const uint32_t*)(ar + 8 * GP);
                a[mt][2] = *(const uint32_t*)(ar + 8);
                a[mt][3] = *(const uint32_t*)(ar + 8 * GP + 8);
            }
            #pragma unroll
            for (int nj = 0; nj < 4; nj++) {
                const __half* br = Bs + (wn * 32 + nj * 8 + g) * GP + k0;
                b[nj][0] = *(const uint32_t*)(br);
                b[nj][1] = *(const uint32_t*)(br + 8);
            }
            #pragma unroll
            for (int mt = 0; mt < 2; mt++)
                #pragma unroll
                for (int nj = 0; nj < 4; nj++)
                    mma_16816(acc[mt][nj],
                              a[mt][0], a[mt][1], a[mt][2], a[mt][3],
                              b[nj][0], b[nj][1]);
        }

        #pragma unroll
        for (int mt = 0; mt < 2; mt++) {
            #pragma unroll
            for (int nj = 0; nj < 4; nj++) {
                int row = bm + wm * 32 + mt * 16 + g;
                int col = nb * 64 + wn * 32 + nj * 8 + tq * 2;
                float2 bb = *(const float2*)(bias + col);
                float v0 = acc[mt][nj][0] + bb.x;
                float v1 = acc[mt][nj][1] + bb.y;
                float v2 = acc[mt][nj][2] + bb.x;
                float v3 = acc[mt][nj][3] + bb.y;
                if (store_half) {
                    __half* o = (__half*)Cout;
                    *(__half2*)(o + (size_t)row * Ntot + col) = __floats2half2_rn(v0, v1);
                    *(__half2*)(o + (size_t)(row + 8) * Ntot + col) = __floats2half2_rn(v2, v3);
                } else {
                    float* o = (float*)Cout;
                    *(float2*)(o + (size_t)row * Ntot + col) = make_float2(v0, v1);
                    *(float2*)(o + (size_t)(row + 8) * Ntot + col) = make_float2(v2, v3);
                }
            }
        }
        __syncthreads();
    }
}

// ---------------------------------------------------------------------------
// Conv-fused HMMA proj GEMM: A tile = dwconv3x3(attn) computed on the fly.
// Block = one image row (b, h, w=0..127) = tokens bm..bm+127. Ntot=192, fp32 out.
// ---------------------------------------------------------------------------
#define CW_OFF  GSM_TOTAL                       // bytes; conv weights after As/Bs
#define CGSM_TOTAL (GSM_TOTAL + (9 * 192 + 192) * 4)   // 84480

__global__ __launch_bounds__(256)
void gemm_conv_hmma_kernel(const __half* __restrict__ attn,
                           const float* __restrict__ wdw,
                           const float* __restrict__ bdw,
                           const float* __restrict__ W,
                           const float* __restrict__ bias,
                           float* __restrict__ Cout)
{
    extern __shared__ __half sh[];
    __half* As = sh;
    __half* Bs = sh + 128 * GP;
    float* cw = (float*)((char*)sh + CW_OFF);   // [9][192]
    float* cb = cw + 9 * 192;                   // [192]

    const int tid  = threadIdx.x;
    const int wid  = tid >> 5, lane = tid & 31;
    const int wm   = wid >> 1;
    const int wn   = wid & 1;
    const int g    = lane >> 2;
    const int tq   = lane & 3;
    const int bm   = blockIdx.x * 128;
    const int bimg = blockIdx.x >> 7;
    const int hrow = blockIdx.x & 127;

    for (int idx = tid; idx < 9 * 192; idx += 256) cw[idx] = wdw[idx];
    if (tid < 192) cb[tid] = bdw[tid];
    __syncthreads();

    // A tile = conv(attn) for pixels (bimg, hrow, w), fp32 math -> fp16
    for (int idx = tid; idx < 128 * 24; idx += 256) {
        int w = idx / 24, c8 = idx % 24, c = c8 * 8;
        float acc[8];
        {
            float4 b0 = *(const float4*)(cb + c);
            float4 b1 = *(const float4*)(cb + c + 4);
            acc[0] = b0.x; acc[1] = b0.y; acc[2] = b0.z; acc[3] = b0.w;
            acc[4] = b1.x; acc[5] = b1.y; acc[6] = b1.z; acc[7] = b1.w;
        }
        #pragma unroll
        for (int ky = 0; ky < 3; ky++) {
            int hh = hrow + ky - 1;
            if ((unsigned)hh > 127u) continue;
            #pragma unroll
            for (int kx = 0; kx < 3; kx++) {
                int ww = w + kx - 1;
                if ((unsigned)ww > 127u) continue;
                uint4 raw = *(const uint4*)(attn +
                    ((size_t)((bimg * 128 + hh) * 128 + ww)) * 192 + c);
                const __half2* xh = (const __half2*)&raw;
                float4 w0 = *(const float4*)(cw + (ky * 3 + kx) * 192 + c);
                float4 w1 = *(const float4*)(cw + (ky * 3 + kx) * 192 + c + 4);
                float wk[8] = {w0.x, w0.y, w0.z, w0.w, w1.x, w1.y, w1.z, w1.w};
                #pragma unroll
                for (int j = 0; j < 4; j++) {
                    float2 f = __half22float2(xh[j]);
                    acc[2 * j]     = fmaf(f.x, wk[2 * j],     acc[2 * j]);
                    acc[2 * j + 1] = fmaf(f.y, wk[2 * j + 1], acc[2 * j + 1]);
                }
            }
        }
        uint4 o;
        __half2* oh = (__half2*)&o;
        #pragma unroll
        for (int j = 0; j < 4; j++)
            oh[j] = __floats2half2_rn(acc[2 * j], acc[2 * j + 1]);
        *(uint4*)(As + w * GP + c) = o;
    }

    for (int nb = 0; nb < 3; nb++) {        // Ntot = 192
        for (int idx = tid; idx < 192 * 64; idx += 256) {
            int k = idx >> 6, nl = idx & 63;
            Bs[nl * GP + k] = __float2half(W[(size_t)k * 192 + nb * 64 + nl]);
        }
        __syncthreads();

        float acc[2][4][4] = {};
        #pragma unroll
        for (int ks = 0; ks < 12; ks++) {
            const int k0 = ks * 16 + tq * 2;
            uint32_t a[2][4], b[4][2];
            #pragma unroll
            for (int mt = 0; mt < 2; mt++) {
                const __half* ar = As + (wm * 32 + mt * 16 + g) * GP + k0;
                a[mt][0] = *(const uint32_t*)(ar);
                a[mt][1] = *(const uint32_t*)(ar + 8 * GP);
                a[mt][2] = *(const uint32_t*)(ar + 8);
                a[mt][3] = *(const uint32_t*)(ar + 8 * GP + 8);
            }
            #pragma unroll
            for (int nj = 0; nj < 4; nj++) {
                const __half* br = Bs + (wn * 32 + nj * 8 + g) * GP + k0;
                b[nj][0] = *(const uint32_t*)(br);
                b[nj][1] = *(const uint32_t*)(br + 8);
            }
            #pragma unroll
            for (int mt = 0; mt < 2; mt++)
                #pragma unroll
                for (int nj = 0; nj < 4; nj++)
                    mma_16816(acc[mt][nj],
                              a[mt][0], a[mt][1], a[mt][2], a[mt][3],
                              b[nj][0], b[nj][1]);
        }

        #pragma unroll
        for (int mt = 0; mt < 2; mt++) {
            #pragma unroll
            for (int nj = 0; nj < 4; nj++) {
                int row = bm + wm * 32 + mt * 16 + g;
                int col = nb * 64 + wn * 32 + nj * 8 + tq * 2;
                float2 bb = *(const float2*)(bias + col);
                *(float2*)(Cout + (size_t)row * 192 + col) =
                    make_float2(acc[mt][nj][0] + bb.x, acc[mt][nj][1] + bb.y);
                *(float2*)(Cout + (size_t)(row + 8) * 192 + col) =
                    make_float2(acc[mt][nj][2] + bb.x, acc[mt][nj][3] + bb.y);
            }
        }
        __syncthreads();
    }
}

// ---------------------------------------------------------------------------
// Tensor-core window attention. Block = one window, 384 thr = 12 warps.
// Warp = (head h = wid/2, row-half mh = wid%2). Q/K smem stride 40 halves,
// V transposed [hd][j] stride 72 halves (both conflict-free for frag loads).
// S = Q@K^T (m16n8k16, fp32 accum), fragment softmax (quad shuffles),
// O = (P_hi + P_lo)@V  (residual split kills fp16-P quantization error).
// ---------------------------------------------------------------------------
#define QK_ST 40
#define VT_ST 72
#define SMK_OFF (6 * 64 * QK_ST)                  // halves
#define SMV_OFF (2 * SMK_OFF)
#define ATT_SMEM ((SMV_OFF + 6 * HD * VT_ST) * 2) // 89088 bytes

__global__ __launch_bounds__(384)
void win_attn_mma_kernel(const __half* __restrict__ qkv, __half* __restrict__ out)
{
    extern __shared__ __half smh[];
    __half* Qs = smh;
    __half* Ks = smh + SMK_OFF;
    __half* Vt = smh + SMV_OFF;

    const int win = blockIdx.x;
    const int b   = win >> 8, rem = win & 255;
    const int wh  = rem >> 4, ww = rem & 15;
    const int tid = threadIdx.x;

    // stage QKV for the 64 window tokens
    for (int idx = tid; idx < 64 * 72; idx += 384) {
        int tok = idx / 72, c16 = idx % 72;
        int ch = c16 * 8;
        int iy = tok >> 3, ix = tok & 7;
        const __half* src = qkv +
            ((size_t)((b * 128 + wh * 8 + iy) * 128 + ww * 8 + ix)) * QKV_N + ch;
        uint4 v = *(const uint4*)src;
        int sec = ch / 192, wi = ch % 192;
        int hh = wi / 32, hc = wi % 32;
        if (sec == 0)
            *(uint4*)(Qs + hh * 64 * QK_ST + tok * QK_ST + hc) = v;
        else if (sec == 1)
            *(uint4*)(Ks + hh * 64 * QK_ST + tok * QK_ST + hc) = v;
        else {
            const __half* hv = (const __half*)&v;
            #pragma unroll
            for (int j = 0; j < 8; j++)
                Vt[hh * HD * VT_ST + (hc + j) * VT_ST + tok] = hv[j];
        }
    }
    __syncthreads();

    const int wid = tid >> 5, lane = tid & 31;
    const int h = wid >> 1, mh = wid & 1;
    const int g = lane >> 2, tq = lane & 3;

    const __half* Qh = Qs + h * 64 * QK_ST;
    const __half* Kh = Ks + h * 64 * QK_ST;
    const __half* Vh = Vt + h * HD * VT_ST;

    // ---- S = Q @ K^T  (rows mh*32..mh*32+31, all 64 cols) ----
    float S[2][8][4] = {};
    #pragma unroll
    for (int ks = 0; ks < 2; ks++) {
        const int k0 = ks * 16 + tq * 2;
        uint32_t bf[8][2];
        #pragma unroll
        for (int n = 0; n < 8; n++) {
            const __half* br = Kh + (n * 8 + g) * QK_ST + k0;
            bf[n][0] = *(const uint32_t*)(br);
            bf[n][1] = *(const uint32_t*)(br + 8);
        }
        #pragma unroll
        for (int mt = 0; mt < 2; mt++) {
            const __half* ar = Qh + (mh * 32 + mt * 16 + g) * QK_ST + k0;
            uint32_t a0 = *(const uint32_t*)(ar);
            uint32_t a1 = *(const uint32_t*)(ar + 8 * QK_ST);
            uint32_t a2 = *(const uint32_t*)(ar + 8);
            uint32_t a3 = *(const uint32_t*)(ar + 8 * QK_ST + 8);
            #pragma unroll
            for (int n = 0; n < 8; n++)
                mma_16816(S[mt][n], a0, a1, a2, a3, bf[n][0], bf[n][1]);
        }
    }

    // ---- softmax on fragments ----
    const float scale = 0.1767766952966369f;   // 1/sqrt(32)
    float inva[2], invb[2];
    #pragma unroll
    for (int mt = 0; mt < 2; mt++) {
        float mxa = -1e30f, mxb = -1e30f;
        #pragma unroll
        for (int n = 0; n < 8; n++) {
            S[mt][n][0] *= scale; S[mt][n][1] *= scale;
            S[mt][n][2] *= scale; S[mt][n][3] *= scale;
            mxa = fmaxf(mxa, fmaxf(S[mt][n][0], S[mt][n][1]));
            mxb = fmaxf(mxb, fmaxf(S[mt][n][2], S[mt][n][3]));
        }
        mxa = fmaxf(mxa, __shfl_xor_sync(0xffffffffu, mxa, 1));
        mxa = fmaxf(mxa, __shfl_xor_sync(0xffffffffu, mxa, 2));
        mxb = fmaxf(mxb, __shfl_xor_sync(0xffffffffu, mxb, 1));
        mxb = fmaxf(mxb, __shfl_xor_sync(0xffffffffu, mxb, 2));
        float sa = 0.f, sb = 0.f;
        #pragma unroll
        for (int n = 0; n < 8; n++) {
            S[mt][n][0] = __expf(S[mt][n][0] - mxa);
            S[mt][n][1] = __expf(S[mt][n][1] - mxa);
            S[mt][n][2] = __expf(S[mt][n][2] - mxb);
            S[mt][n][3] = __expf(S[mt][n][3] - mxb);
            sa += S[mt][n][0] + S[mt][n][1];
            sb += S[mt][n][2] + S[mt][n][3];
        }
        sa += __shfl_xor_sync(0xffffffffu, sa, 1);
        sa += __shfl_xor_sync(0xffffffffu, sa, 2);
        sb += __shfl_xor_sync(0xffffffffu, sb, 1);
        sb += __shfl_xor_sync(0xffffffffu, sb, 2);
        inva[mt] = 1.0f / sa;
        invb[mt] = 1.0f / sb;
    }

    // ---- O = (P_hi + P_lo) @ V ----
    float O[2][4][4] = {};
    #pragma unroll
    for (int mt = 0; mt < 2; mt++) {
        #pragma unroll
        for (int kt = 0; kt < 4; kt++) {
            const float* s0 = S[mt][2 * kt];
            const float* s1 = S[mt][2 * kt + 1];
            uint32_t ah[4], al[4];
            #pragma unroll
            for (int q = 0; q < 4; q++) {
                const float* sp = (q < 2) ? s0 : s1;
                float x0 = sp[(q & 1) * 2], x1 = sp[(q & 1) * 2 + 1];
                __half2 hi = __floats2half2_rn(x0, x1);
                ah[q] = *(const uint32_t*)&hi;
                float2 back = __half22float2(hi);
                __half2 lo = __floats2half2_rn(x0 - back.x, x1 - back.y);
                al[q] = *(const uint32_t*)&lo;
            }
            #pragma unroll
            for (int nv = 0; nv < 4; nv++) {
                const __half* br = Vh + (nv * 8 + g) * VT_ST + kt * 16 + tq * 2;
                uint32_t b0 = *(const uint32_t*)(br);
                uint32_t b1 = *(const uint32_t*)(br + 8);
                mma_16816(O[mt][nv], ah[0], ah[1], ah[2], ah[3], b0, b1);
                mma_16816(O[mt][nv], al[0], al[1], al[2], al[3], b0, b1);
            }
        }
    }

    // ---- normalize + store ----
    #pragma unroll
    for (int mt = 0; mt < 2; mt++) {
        int ta = mh * 32 + mt * 16 + g;
        int tb = ta + 8;
        int iya = ta >> 3, ixa = ta & 7;
        int iyb = tb >> 3, ixb = tb & 7;
        __half* pa = out + ((size_t)((b * 128 + wh * 8 + iya) * 128 + ww * 8 + ixa)) * C_DIM;
        __half* pb = out + ((size_t)((b * 128 + wh * 8 + iyb) * 128 + ww * 8 + ixb)) * C_DIM;
        #pragma unroll
        for (int nv = 0; nv < 4; nv++) {
            int col = h * 32 + nv * 8 + tq * 2;
            *(__half2*)(pa + col) =
                __floats2half2_rn(O[mt][nv][0] * inva[mt], O[mt][nv][1] * inva[mt]);
            *(__half2*)(pb + col) =
                __floats2half2_rn(O[mt][nv][2] * invb[mt], O[mt][nv][3] * invb[mt]);
        }
    }
}

// ---------------------------------------------------------------------------
extern "C" void kernel_launch(void* const* d_in, const int* in_sizes, int n_in,
                              void* d_out, int out_size)
{
    const float* x      = (const float*)d_in[0];
    const float* w_qkv  = (const float*)d_in[1];
    const float* b_qkv  = (const float*)d_in[2];
    const float* w_dw   = (const float*)d_in[3];
    const float* b_dw   = (const float*)d_in[4];
    const float* w_proj = (const float*)d_in[5];
    const float* b_proj = (const float*)d_in[6];
    float* out = (float*)d_out;

    __half *qkvh, *attnh;
    cudaGetSymbolAddress((void**)&qkvh,  g_qkvh);
    cudaGetSymbolAddress((void**)&attnh, g_attnh);

    // idempotent; called every time (no static guards allowed)
    cudaFuncSetAttribute(gemm_hmma_kernel,
                         cudaFuncAttributeMaxDynamicSharedMemorySize, GSM_TOTAL);
    cudaFuncSetAttribute(gemm_conv_hmma_kernel,
                         cudaFuncAttributeMaxDynamicSharedMemorySize, CGSM_TOTAL);
    cudaFuncSetAttribute(win_attn_mma_kernel,
                         cudaFuncAttributeMaxDynamicSharedMemorySize, ATT_SMEM);

    // 1) qkv = x @ w_qkv + b_qkv   -> fp16 [131072, 576]
    gemm_hmma_kernel<<<M_TOK / 128, 256, GSM_TOTAL>>>(
        x, 0, w_qkv, b_qkv, qkvh, QKV_N, 1);

    // 2) tensor-core window attention (fp16 -> fp16)
    win_attn_mma_kernel<<<2048, 384, ATT_SMEM>>>(qkvh, attnh);

    // 3+4) fused dwconv3x3 + proj GEMM -> fp32 out
    gemm_conv_hmma_kernel<<<M_TOK / 128, 256, CGSM_TOTAL>>>(
        attnh, w_dw, b_dw, w_proj, b_proj, out);
}